// round 1
// baseline (speedup 1.0000x reference)
#include <cuda_runtime.h>

// MultiScaleHypercubeLayer fused kernel.
// x: [B=4, S=4096, D=2048] f32
// W_to: [4, 2048], W_from: [2048, 4], log_temp scalar, scale scalar.
// out[b,s,d] = x + scale * sum_j q_j * W_from[d,j]
// where q = softmax(-cdist(x@W_to^T, V)/temp) @ V,  V = corners of {0,1}^4.
//
// One block (256 threads) per token. x row held in registers: read once, write once.

#define D_MODEL 2048
#define THREADS 256
#define PER_THR 8  // D_MODEL / THREADS

__global__ void __launch_bounds__(THREADS)
hypercube_kernel(const float* __restrict__ x,
                 const float* __restrict__ W_to,
                 const float* __restrict__ W_from,
                 const float* __restrict__ log_temp,
                 const float* __restrict__ scale_p,
                 float* __restrict__ out)
{
    const int token = blockIdx.x;
    const int tid   = threadIdx.x;
    const float* xr = x   + (size_t)token * D_MODEL;
    float*      orow = out + (size_t)token * D_MODEL;

    __shared__ float s_part[8][4];   // per-warp partial z
    __shared__ float s_q[4];         // scale * quantized (broadcast)

    const int d0 = tid * PER_THR;

    // ---- Phase 1: load x (kept in registers), partial dot with W_to rows ----
    float4 xa = *reinterpret_cast<const float4*>(xr + d0);
    float4 xb = *reinterpret_cast<const float4*>(xr + d0 + 4);

    float z[4];
#pragma unroll
    for (int k = 0; k < 4; k++) {
        float4 wa = __ldg(reinterpret_cast<const float4*>(W_to + k * D_MODEL + d0));
        float4 wb = __ldg(reinterpret_cast<const float4*>(W_to + k * D_MODEL + d0 + 4));
        z[k] = xa.x * wa.x + xa.y * wa.y + xa.z * wa.z + xa.w * wa.w
             + xb.x * wb.x + xb.y * wb.y + xb.z * wb.z + xb.w * wb.w;
    }

    // warp reduction of 4 partials
#pragma unroll
    for (int off = 16; off > 0; off >>= 1) {
#pragma unroll
        for (int k = 0; k < 4; k++)
            z[k] += __shfl_xor_sync(0xffffffffu, z[k], off);
    }

    const int warp = tid >> 5;
    const int lane = tid & 31;
    if (lane == 0) {
#pragma unroll
        for (int k = 0; k < 4; k++) s_part[warp][k] = z[k];
    }
    __syncthreads();

    // ---- Phase 2: thread 0 finishes reduction + 16-corner softmax ----
    if (tid == 0) {
        float zz[4] = {0.f, 0.f, 0.f, 0.f};
#pragma unroll
        for (int w = 0; w < 8; w++)
#pragma unroll
            for (int k = 0; k < 4; k++) zz[k] += s_part[w][k];

        float temp  = fminf(fmaxf(expf(log_temp[0]), 0.01f), 5.0f);
        float inv_t = 1.0f / temp;

        // V[k][j] = bit (3-j) of k   (itertools.product ordering: dim 0 = MSB)
        float dist[16];
        float mn = 1e30f;
#pragma unroll
        for (int k = 0; k < 16; k++) {
            float s = 0.f;
#pragma unroll
            for (int j = 0; j < 4; j++) {
                float v = (float)((k >> (3 - j)) & 1);
                float df = zz[j] - v;
                s += df * df;
            }
            dist[k] = sqrtf(s);
            mn = fminf(mn, dist[k]);
        }

        float wsum = 0.f;
        float q[4] = {0.f, 0.f, 0.f, 0.f};
#pragma unroll
        for (int k = 0; k < 16; k++) {
            float w = expf(-(dist[k] - mn) * inv_t);
            wsum += w;
#pragma unroll
            for (int j = 0; j < 4; j++)
                q[j] += w * (float)((k >> (3 - j)) & 1);
        }

        float sc = scale_p[0] / wsum;
#pragma unroll
        for (int j = 0; j < 4; j++) s_q[j] = q[j] * sc;
    }
    __syncthreads();

    // ---- Phase 3: residual add + rank-4 outer product with W_from ----
    const float q0 = s_q[0], q1 = s_q[1], q2 = s_q[2], q3 = s_q[3];

#pragma unroll
    for (int c = 0; c < 2; c++) {
        const float4 xv = c ? xb : xa;
        const int d = d0 + c * 4;
        // W_from row d is 4 contiguous floats -> one float4 per output element
        float4 w0 = __ldg(reinterpret_cast<const float4*>(W_from + (size_t)(d + 0) * 4));
        float4 w1 = __ldg(reinterpret_cast<const float4*>(W_from + (size_t)(d + 1) * 4));
        float4 w2 = __ldg(reinterpret_cast<const float4*>(W_from + (size_t)(d + 2) * 4));
        float4 w3 = __ldg(reinterpret_cast<const float4*>(W_from + (size_t)(d + 3) * 4));
        float4 o;
        o.x = xv.x + q0 * w0.x + q1 * w0.y + q2 * w0.z + q3 * w0.w;
        o.y = xv.y + q0 * w1.x + q1 * w1.y + q2 * w1.z + q3 * w1.w;
        o.z = xv.z + q0 * w2.x + q1 * w2.y + q2 * w2.z + q3 * w2.w;
        o.w = xv.w + q0 * w3.x + q1 * w3.y + q2 * w3.z + q3 * w3.w;
        *reinterpret_cast<float4*>(orow + d) = o;
    }
}

extern "C" void kernel_launch(void* const* d_in, const int* in_sizes, int n_in,
                              void* d_out, int out_size)
{
    const float* x        = (const float*)d_in[0];
    const float* W_to     = (const float*)d_in[1];
    const float* W_from   = (const float*)d_in[2];
    const float* log_temp = (const float*)d_in[3];
    const float* scale    = (const float*)d_in[4];
    float* out = (float*)d_out;

    const int n_tokens = in_sizes[0] / D_MODEL;  // B*S = 16384

    hypercube_kernel<<<n_tokens, THREADS>>>(x, W_to, W_from, log_temp, scale, out);
}

// round 2
// speedup vs baseline: 1.6785x; 1.6785x over previous
#include <cuda_runtime.h>

// MultiScaleHypercubeLayer fused kernel, R2.
// x: [B*S=16384, D=2048] f32; W_to: [4,2048]; W_from: [2048,4]; scalars.
// out[t,d] = x[t,d] + scale * sum_j q_j(t) * W_from[d,j]
// q(t) = softmax(-||x_t W_to^T - V||/temp) @ V,  V = corners of {0,1}^4.
//
// 512 threads/block, each thread owns 4 consecutive d (weights cached in regs),
// block processes TOK_PER_BLOCK tokens. Per token: one LDG.128 + one STG.128
// per thread (compulsory traffic only). Softmax on warp 0 via butterfly shfl.

#define D_MODEL 2048
#define THREADS 512
#define TOK_PER_BLOCK 16

__global__ void __launch_bounds__(THREADS, 2)
hypercube_kernel(const float* __restrict__ x,
                 const float* __restrict__ W_to,
                 const float* __restrict__ W_from,
                 const float* __restrict__ log_temp,
                 const float* __restrict__ scale_p,
                 float* __restrict__ out,
                 int n_tokens)
{
    const int tid  = threadIdx.x;
    const int warp = tid >> 5;
    const int lane = tid & 31;
    const int d0   = tid * 4;

    __shared__ float4 s_part[16];  // per-warp partial z (16 warps)
    __shared__ float4 s_q;         // scale * quantized / wsum

    // ---- one-time: cache weight slices in registers ----
    float4 wt0 = __ldg(reinterpret_cast<const float4*>(W_to + 0 * D_MODEL + d0));
    float4 wt1 = __ldg(reinterpret_cast<const float4*>(W_to + 1 * D_MODEL + d0));
    float4 wt2 = __ldg(reinterpret_cast<const float4*>(W_to + 2 * D_MODEL + d0));
    float4 wt3 = __ldg(reinterpret_cast<const float4*>(W_to + 3 * D_MODEL + d0));

    float4 wf0 = __ldg(reinterpret_cast<const float4*>(W_from + (size_t)(d0 + 0) * 4));
    float4 wf1 = __ldg(reinterpret_cast<const float4*>(W_from + (size_t)(d0 + 1) * 4));
    float4 wf2 = __ldg(reinterpret_cast<const float4*>(W_from + (size_t)(d0 + 2) * 4));
    float4 wf3 = __ldg(reinterpret_cast<const float4*>(W_from + (size_t)(d0 + 3) * 4));

    const float temp  = fminf(fmaxf(expf(__ldg(log_temp)), 0.01f), 5.0f);
    const float inv_t = 1.0f / temp;
    const float scale = __ldg(scale_p);

    const int t0    = blockIdx.x * TOK_PER_BLOCK;
    const int t_end = min(TOK_PER_BLOCK, n_tokens - t0);

    const float* xp = x   + (size_t)t0 * D_MODEL + d0;
    float*       op = out + (size_t)t0 * D_MODEL + d0;

    float4 xv = *reinterpret_cast<const float4*>(xp);

    for (int i = 0; i < t_end; i++) {
        // ---- partial projection z[k] = <x_slice, W_to[k]_slice> ----
        float z0 = xv.x * wt0.x + xv.y * wt0.y + xv.z * wt0.z + xv.w * wt0.w;
        float z1 = xv.x * wt1.x + xv.y * wt1.y + xv.z * wt1.z + xv.w * wt1.w;
        float z2 = xv.x * wt2.x + xv.y * wt2.y + xv.z * wt2.z + xv.w * wt2.w;
        float z3 = xv.x * wt3.x + xv.y * wt3.y + xv.z * wt3.z + xv.w * wt3.w;

        // prefetch next token's x — latency hides under reduction/softmax
        float4 xn = make_float4(0.f, 0.f, 0.f, 0.f);
        if (i + 1 < t_end)
            xn = *reinterpret_cast<const float4*>(xp + (size_t)(i + 1) * D_MODEL);

        // ---- warp butterfly reduce (all lanes end with warp sums) ----
#pragma unroll
        for (int off = 16; off > 0; off >>= 1) {
            z0 += __shfl_xor_sync(0xffffffffu, z0, off);
            z1 += __shfl_xor_sync(0xffffffffu, z1, off);
            z2 += __shfl_xor_sync(0xffffffffu, z2, off);
            z3 += __shfl_xor_sync(0xffffffffu, z3, off);
        }
        if (lane == 0) s_part[warp] = make_float4(z0, z1, z2, z3);
        __syncthreads();

        // ---- warp 0: cross-warp combine + 16-corner softmax ----
        if (warp == 0) {
            float4 p = (lane < 16) ? s_part[lane] : make_float4(0.f, 0.f, 0.f, 0.f);
#pragma unroll
            for (int off = 16; off > 0; off >>= 1) {
                p.x += __shfl_xor_sync(0xffffffffu, p.x, off);
                p.y += __shfl_xor_sync(0xffffffffu, p.y, off);
                p.z += __shfl_xor_sync(0xffffffffu, p.z, off);
                p.w += __shfl_xor_sync(0xffffffffu, p.w, off);
            }
            // lane k (k<16) owns corner k; V[k][j] = bit (3-j) of k
            const float v0 = (float)((lane >> 3) & 1);
            const float v1 = (float)((lane >> 2) & 1);
            const float v2 = (float)((lane >> 1) & 1);
            const float v3 = (float)(lane & 1);

            float dx = p.x - v0, dy = p.y - v1, dz = p.z - v2, dw = p.w - v3;
            float dist = sqrtf(dx * dx + dy * dy + dz * dz + dw * dw);
            if (lane >= 16) dist = 3.0e38f;

            float mn = dist;
#pragma unroll
            for (int off = 16; off > 0; off >>= 1)
                mn = fminf(mn, __shfl_xor_sync(0xffffffffu, mn, off));

            float w  = (lane < 16) ? expf(-(dist - mn) * inv_t) : 0.f;
            float q0 = w * v0, q1 = w * v1, q2 = w * v2, q3 = w * v3;
            float ws = w;
#pragma unroll
            for (int off = 16; off > 0; off >>= 1) {
                ws += __shfl_xor_sync(0xffffffffu, ws, off);
                q0 += __shfl_xor_sync(0xffffffffu, q0, off);
                q1 += __shfl_xor_sync(0xffffffffu, q1, off);
                q2 += __shfl_xor_sync(0xffffffffu, q2, off);
                q3 += __shfl_xor_sync(0xffffffffu, q3, off);
            }
            if (lane == 0) {
                const float sc = scale / ws;
                s_q = make_float4(q0 * sc, q1 * sc, q2 * sc, q3 * sc);
            }
        }
        __syncthreads();

        // ---- residual + rank-4 expansion, compulsory store ----
        const float4 q = s_q;
        float4 o;
        o.x = xv.x + q.x * wf0.x + q.y * wf0.y + q.z * wf0.z + q.w * wf0.w;
        o.y = xv.y + q.x * wf1.x + q.y * wf1.y + q.z * wf1.z + q.w * wf1.w;
        o.z = xv.z + q.x * wf2.x + q.y * wf2.y + q.z * wf2.z + q.w * wf2.w;
        o.w = xv.w + q.x * wf3.x + q.y * wf3.y + q.z * wf3.z + q.w * wf3.w;
        *reinterpret_cast<float4*>(op + (size_t)i * D_MODEL) = o;

        xv = xn;
    }
}

extern "C" void kernel_launch(void* const* d_in, const int* in_sizes, int n_in,
                              void* d_out, int out_size)
{
    const float* x        = (const float*)d_in[0];
    const float* W_to     = (const float*)d_in[1];
    const float* W_from   = (const float*)d_in[2];
    const float* log_temp = (const float*)d_in[3];
    const float* scale    = (const float*)d_in[4];
    float* out = (float*)d_out;

    const int n_tokens = in_sizes[0] / D_MODEL;  // B*S = 16384
    const int blocks   = (n_tokens + TOK_PER_BLOCK - 1) / TOK_PER_BLOCK;

    hypercube_kernel<<<blocks, THREADS>>>(x, W_to, W_from, log_temp, scale, out,
                                          n_tokens);
}

// round 6
// speedup vs baseline: 2.5947x; 1.5458x over previous
#include <cuda_runtime.h>

// MultiScaleHypercubeLayer fused kernel, R3 design (third resubmit — rounds 3-5
// all failed on GPU-broker infrastructure before any kernel launch).
// x: [16384, 2048] f32; W_to: [4,2048]; W_from: [2048,4]; scalars.
//
// Block = 512 threads = 16 warps, processes T=16 tokens with only TWO barriers:
//   Phase A: per-thread z partials for all 16 tokens, 6-shuffle transpose-reduce.
//   Phase B: warp w computes softmax for token w (16 tokens fully parallel).
//   Phase C: residual + rank-4 epilogue; x reloaded (L1-hot).
// Weights live in registers (each thread owns a fixed 4-wide d slice).

#define D_MODEL 2048
#define THREADS 512
#define T 16

__global__ void __launch_bounds__(THREADS, 2)
hypercube_kernel(const float* __restrict__ x,
                 const float* __restrict__ W_to,
                 const float* __restrict__ W_from,
                 const float* __restrict__ log_temp,
                 const float* __restrict__ scale_p,
                 float* __restrict__ out)
{
    const int tid  = threadIdx.x;
    const int warp = tid >> 5;
    const int lane = tid & 31;
    const int d0   = tid * 4;

    __shared__ float4 s_part[T][16];  // [token][warp] -> (z0,z1,z2,z3) warp sums
    __shared__ float4 s_q[T];         // scale * quantized / wsum per token

    // ---- weights cached in registers (one-time) ----
    const float4 wt0 = __ldg(reinterpret_cast<const float4*>(W_to + 0 * D_MODEL + d0));
    const float4 wt1 = __ldg(reinterpret_cast<const float4*>(W_to + 1 * D_MODEL + d0));
    const float4 wt2 = __ldg(reinterpret_cast<const float4*>(W_to + 2 * D_MODEL + d0));
    const float4 wt3 = __ldg(reinterpret_cast<const float4*>(W_to + 3 * D_MODEL + d0));

    const float4 wf0 = __ldg(reinterpret_cast<const float4*>(W_from + (size_t)(d0 + 0) * 4));
    const float4 wf1 = __ldg(reinterpret_cast<const float4*>(W_from + (size_t)(d0 + 1) * 4));
    const float4 wf2 = __ldg(reinterpret_cast<const float4*>(W_from + (size_t)(d0 + 2) * 4));
    const float4 wf3 = __ldg(reinterpret_cast<const float4*>(W_from + (size_t)(d0 + 3) * 4));

    const float temp  = fminf(fmaxf(expf(__ldg(log_temp)), 0.01f), 5.0f);
    const float inv_t = 1.0f / temp;
    const float scale = __ldg(scale_p);

    const size_t base = (size_t)blockIdx.x * T * D_MODEL + d0;
    const float* xp = x   + base;
    float*       op = out + base;

    // ================= Phase A: projections for all T tokens =================
    float4 xv = *reinterpret_cast<const float4*>(xp);

#pragma unroll
    for (int t = 0; t < T; t++) {
        float4 xn = make_float4(0.f, 0.f, 0.f, 0.f);
        if (t + 1 < T)
            xn = *reinterpret_cast<const float4*>(xp + (size_t)(t + 1) * D_MODEL);

        float z0 = xv.x * wt0.x + xv.y * wt0.y + xv.z * wt0.z + xv.w * wt0.w;
        float z1 = xv.x * wt1.x + xv.y * wt1.y + xv.z * wt1.z + xv.w * wt1.w;
        float z2 = xv.x * wt2.x + xv.y * wt2.y + xv.z * wt2.z + xv.w * wt2.w;
        float z3 = xv.x * wt3.x + xv.y * wt3.y + xv.z * wt3.z + xv.w * wt3.w;

        // transpose-reduce: 6 shuffles instead of 20.
        // Level 1 (xor 1): pair-sum, splitting k in {0,1} / {2,3} by lane bit0.
        float a01 = (lane & 1) ? z1 : z0;
        float b01 = (lane & 1) ? z0 : z1;
        a01 += __shfl_xor_sync(0xffffffffu, b01, 1);
        float a23 = (lane & 1) ? z3 : z2;
        float b23 = (lane & 1) ? z2 : z3;
        a23 += __shfl_xor_sync(0xffffffffu, b23, 1);
        // Level 2 (xor 2): quad-sum; lane now owns k = lane&3.
        float c = (lane & 2) ? a23 : a01;
        float d = (lane & 2) ? a01 : a23;
        c += __shfl_xor_sync(0xffffffffu, d, 2);
        // Levels 3-5: plain butterfly -> full warp sum of z[lane&3].
        c += __shfl_xor_sync(0xffffffffu, c, 4);
        c += __shfl_xor_sync(0xffffffffu, c, 8);
        c += __shfl_xor_sync(0xffffffffu, c, 16);

        if (lane < 4)
            reinterpret_cast<float*>(&s_part[t][warp])[lane] = c;

        xv = xn;
    }
    __syncthreads();

    // ================= Phase B: warp w -> softmax for token w ================
    {
        const int t = warp;
        float4 p = (lane < 16) ? s_part[t][lane]
                               : make_float4(0.f, 0.f, 0.f, 0.f);
        // sum over the 16 per-warp partials (4 butterfly levels)
#pragma unroll
        for (int off = 1; off <= 8; off <<= 1) {
            p.x += __shfl_xor_sync(0xffffffffu, p.x, off);
            p.y += __shfl_xor_sync(0xffffffffu, p.y, off);
            p.z += __shfl_xor_sync(0xffffffffu, p.z, off);
            p.w += __shfl_xor_sync(0xffffffffu, p.w, off);
        }
        // lane k < 16 owns corner k; V[k][j] = bit (3-j) of k
        const float v0 = (float)((lane >> 3) & 1);
        const float v1 = (float)((lane >> 2) & 1);
        const float v2 = (float)((lane >> 1) & 1);
        const float v3 = (float)(lane & 1);

        const float dx = p.x - v0, dy = p.y - v1, dz = p.z - v2, dw = p.w - v3;
        const float dist = sqrtf(dx * dx + dy * dy + dz * dz + dw * dw);
        // dist >= 0 -> exp(-dist/temp) in (0,1]; no max-subtraction needed.
        float w  = (lane < 16) ? __expf(-dist * inv_t) : 0.f;
        float ws = w;
        float q0 = w * v0, q1 = w * v1, q2 = w * v2, q3 = w * v3;
#pragma unroll
        for (int off = 1; off <= 8; off <<= 1) {
            ws += __shfl_xor_sync(0xffffffffu, ws, off);
            q0 += __shfl_xor_sync(0xffffffffu, q0, off);
            q1 += __shfl_xor_sync(0xffffffffu, q1, off);
            q2 += __shfl_xor_sync(0xffffffffu, q2, off);
            q3 += __shfl_xor_sync(0xffffffffu, q3, off);
        }
        if (lane == 0) {
            const float sc = scale / ws;
            s_q[t] = make_float4(q0 * sc, q1 * sc, q2 * sc, q3 * sc);
        }
    }
    __syncthreads();

    // ================= Phase C: residual + rank-4 epilogue ===================
#pragma unroll
    for (int t = 0; t < T; t++) {
        const float4 q  = s_q[t];
        const float4 xr = *reinterpret_cast<const float4*>(xp + (size_t)t * D_MODEL);
        float4 o;
        o.x = xr.x + q.x * wf0.x + q.y * wf0.y + q.z * wf0.z + q.w * wf0.w;
        o.y = xr.y + q.x * wf1.x + q.y * wf1.y + q.z * wf1.z + q.w * wf1.w;
        o.z = xr.z + q.x * wf2.x + q.y * wf2.y + q.z * wf2.z + q.w * wf2.w;
        o.w = xr.w + q.x * wf3.x + q.y * wf3.y + q.z * wf3.z + q.w * wf3.w;
        *reinterpret_cast<float4*>(op + (size_t)t * D_MODEL) = o;
    }
}

extern "C" void kernel_launch(void* const* d_in, const int* in_sizes, int n_in,
                              void* d_out, int out_size)
{
    const float* x        = (const float*)d_in[0];
    const float* W_to     = (const float*)d_in[1];
    const float* W_from   = (const float*)d_in[2];
    const float* log_temp = (const float*)d_in[3];
    const float* scale    = (const float*)d_in[4];
    float* out = (float*)d_out;

    const int n_tokens = in_sizes[0] / D_MODEL;  // 16384
    const int blocks   = n_tokens / T;           // 1024

    hypercube_kernel<<<blocks, THREADS>>>(x, W_to, W_from, log_temp, scale, out);
}

// round 10
// speedup vs baseline: 2.7268x; 1.0509x over previous
#include <cuda_runtime.h>

// MultiScaleHypercubeLayer fused kernel, R7 design (third resubmit — rounds
// 7-9 all hit GPU-broker acquisition timeouts; kernel never measured).
// x: [16384, 2048] f32; W_to: [4,2048]; W_from: [2048,4]; scalars.
//
// vs R3: Phase A now front-batches 8 independent LDG.128 per group (MLP=8,
// was 2) to collapse exposed DRAM latency; W_from loads deferred to Phase C
// so the x-prefetch registers fit under the 64-reg / 2-CTA cap.
//
// Block = 512 threads = 16 warps, T=16 tokens, two barriers total:
//   Phase A: 2 groups x 8 tokens; batch loads, then compute + 6-shuffle reduce.
//   Phase B: warp w computes softmax for token w (16 tokens in parallel).
//   Phase C: residual + rank-4 epilogue; x reload is L2/L1-hot.

#define D_MODEL 2048
#define THREADS 512
#define T 16
#define GRP 8

__global__ void __launch_bounds__(THREADS, 2)
hypercube_kernel(const float* __restrict__ x,
                 const float* __restrict__ W_to,
                 const float* __restrict__ W_from,
                 const float* __restrict__ log_temp,
                 const float* __restrict__ scale_p,
                 float* __restrict__ out)
{
    const int tid  = threadIdx.x;
    const int warp = tid >> 5;
    const int lane = tid & 31;
    const int d0   = tid * 4;

    __shared__ float4 s_part[T][16];  // [token][warp] -> (z0,z1,z2,z3) warp sums
    __shared__ float4 s_q[T];         // scale * quantized / wsum per token

    const float temp  = fminf(fmaxf(expf(__ldg(log_temp)), 0.01f), 5.0f);
    const float inv_t = 1.0f / temp;
    const float scale = __ldg(scale_p);

    const size_t base = (size_t)blockIdx.x * T * D_MODEL + d0;
    const float* xp = x   + base;
    float*       op = out + base;

    // ---- W_to slices in registers (live through Phase A only) ----
    const float4 wt0 = __ldg(reinterpret_cast<const float4*>(W_to + 0 * D_MODEL + d0));
    const float4 wt1 = __ldg(reinterpret_cast<const float4*>(W_to + 1 * D_MODEL + d0));
    const float4 wt2 = __ldg(reinterpret_cast<const float4*>(W_to + 2 * D_MODEL + d0));
    const float4 wt3 = __ldg(reinterpret_cast<const float4*>(W_to + 3 * D_MODEL + d0));

    // ================= Phase A: projections, 2 groups of 8 tokens ============
#pragma unroll
    for (int g = 0; g < T / GRP; g++) {
        float4 xr[GRP];
        // front-batched independent loads: MLP = 8
#pragma unroll
        for (int u = 0; u < GRP; u++)
            xr[u] = *reinterpret_cast<const float4*>(
                xp + (size_t)(g * GRP + u) * D_MODEL);

#pragma unroll
        for (int u = 0; u < GRP; u++) {
            const int t = g * GRP + u;
            const float4 xv = xr[u];

            float z0 = xv.x * wt0.x + xv.y * wt0.y + xv.z * wt0.z + xv.w * wt0.w;
            float z1 = xv.x * wt1.x + xv.y * wt1.y + xv.z * wt1.z + xv.w * wt1.w;
            float z2 = xv.x * wt2.x + xv.y * wt2.y + xv.z * wt2.z + xv.w * wt2.w;
            float z3 = xv.x * wt3.x + xv.y * wt3.y + xv.z * wt3.z + xv.w * wt3.w;

            // transpose-reduce: 6 shuffles.
            float a01 = (lane & 1) ? z1 : z0;
            float b01 = (lane & 1) ? z0 : z1;
            a01 += __shfl_xor_sync(0xffffffffu, b01, 1);
            float a23 = (lane & 1) ? z3 : z2;
            float b23 = (lane & 1) ? z2 : z3;
            a23 += __shfl_xor_sync(0xffffffffu, b23, 1);
            float c = (lane & 2) ? a23 : a01;
            float d = (lane & 2) ? a01 : a23;
            c += __shfl_xor_sync(0xffffffffu, d, 2);
            c += __shfl_xor_sync(0xffffffffu, c, 4);
            c += __shfl_xor_sync(0xffffffffu, c, 8);
            c += __shfl_xor_sync(0xffffffffu, c, 16);

            if (lane < 4)
                reinterpret_cast<float*>(&s_part[t][warp])[lane] = c;
        }
    }
    __syncthreads();

    // ================= Phase B: warp w -> softmax for token w ================
    {
        const int t = warp;
        float4 p = (lane < 16) ? s_part[t][lane]
                               : make_float4(0.f, 0.f, 0.f, 0.f);
#pragma unroll
        for (int off = 1; off <= 8; off <<= 1) {
            p.x += __shfl_xor_sync(0xffffffffu, p.x, off);
            p.y += __shfl_xor_sync(0xffffffffu, p.y, off);
            p.z += __shfl_xor_sync(0xffffffffu, p.z, off);
            p.w += __shfl_xor_sync(0xffffffffu, p.w, off);
        }
        // lane k < 16 owns corner k; V[k][j] = bit (3-j) of k
        const float v0 = (float)((lane >> 3) & 1);
        const float v1 = (float)((lane >> 2) & 1);
        const float v2 = (float)((lane >> 1) & 1);
        const float v3 = (float)(lane & 1);

        const float dx = p.x - v0, dy = p.y - v1, dz = p.z - v2, dw = p.w - v3;
        const float dist = sqrtf(dx * dx + dy * dy + dz * dz + dw * dw);
        // dist >= 0 -> exp(-dist/temp) in (0,1]; no max-subtraction needed.
        float w  = (lane < 16) ? __expf(-dist * inv_t) : 0.f;
        float ws = w;
        float q0 = w * v0, q1 = w * v1, q2 = w * v2, q3 = w * v3;
#pragma unroll
        for (int off = 1; off <= 8; off <<= 1) {
            ws += __shfl_xor_sync(0xffffffffu, ws, off);
            q0 += __shfl_xor_sync(0xffffffffu, q0, off);
            q1 += __shfl_xor_sync(0xffffffffu, q1, off);
            q2 += __shfl_xor_sync(0xffffffffu, q2, off);
            q3 += __shfl_xor_sync(0xffffffffu, q3, off);
        }
        if (lane == 0) {
            const float sc = scale / ws;
            s_q[t] = make_float4(q0 * sc, q1 * sc, q2 * sc, q3 * sc);
        }
    }
    __syncthreads();

    // ================= Phase C: residual + rank-4 epilogue ===================
    // W_from slices loaded here (L2 hits); wt/x-batch registers are dead now.
    const float4 wf0 = __ldg(reinterpret_cast<const float4*>(W_from + (size_t)(d0 + 0) * 4));
    const float4 wf1 = __ldg(reinterpret_cast<const float4*>(W_from + (size_t)(d0 + 1) * 4));
    const float4 wf2 = __ldg(reinterpret_cast<const float4*>(W_from + (size_t)(d0 + 2) * 4));
    const float4 wf3 = __ldg(reinterpret_cast<const float4*>(W_from + (size_t)(d0 + 3) * 4));

#pragma unroll
    for (int t = 0; t < T; t++) {
        const float4 q  = s_q[t];
        const float4 xv = *reinterpret_cast<const float4*>(xp + (size_t)t * D_MODEL);
        float4 o;
        o.x = xv.x + q.x * wf0.x + q.y * wf0.y + q.z * wf0.z + q.w * wf0.w;
        o.y = xv.y + q.x * wf1.x + q.y * wf1.y + q.z * wf1.z + q.w * wf1.w;
        o.z = xv.z + q.x * wf2.x + q.y * wf2.y + q.z * wf2.z + q.w * wf2.w;
        o.w = xv.w + q.x * wf3.x + q.y * wf3.y + q.z * wf3.z + q.w * wf3.w;
        *reinterpret_cast<float4*>(op + (size_t)t * D_MODEL) = o;
    }
}

extern "C" void kernel_launch(void* const* d_in, const int* in_sizes, int n_in,
                              void* d_out, int out_size)
{
    const float* x        = (const float*)d_in[0];
    const float* W_to     = (const float*)d_in[1];
    const float* W_from   = (const float*)d_in[2];
    const float* log_temp = (const float*)d_in[3];
    const float* scale    = (const float*)d_in[4];
    float* out = (float*)d_out;

    const int n_tokens = in_sizes[0] / D_MODEL;  // 16384
    const int blocks   = n_tokens / T;           // 1024

    hypercube_kernel<<<blocks, THREADS>>>(x, W_to, W_from, log_temp, scale, out);
}